// round 1
// baseline (speedup 1.0000x reference)
#include <cuda_runtime.h>
#include <math.h>

#define B_  2
#define S_  2048
#define D_  1024
#define H_  16
#define HD_ 64
#define M_  (B_*S_)   // 4096

// Scratch for rotated Q/K/V in [B,H,S,HD] layout (16 MB each, static => legal)
__device__ float g_Q[B_*H_*S_*HD_];
__device__ float g_K[B_*H_*S_*HD_];
__device__ float g_V[B_*H_*S_*HD_];

// ---------------------------------------------------------------------------
// Kernel 1: fused QKV projection GEMM + RoPE epilogue.
//   X:(4096,1024) @ W:(1024,1024), blockIdx.z selects {Wq,Wk,Wv}.
//   Tile 128x128xBK16, 256 threads, 8x8 per-thread micro-tile.
//   Epilogue applies rotary (to q, k AND v, per reference) and writes
//   directly into [B,H,S,HD] layout.
// ---------------------------------------------------------------------------
#define BM 128
#define BN 128
#define BK 16

__global__ __launch_bounds__(256) void qkv_rope_kernel(
    const float* __restrict__ X,
    const float* __restrict__ Wq,
    const float* __restrict__ Wk,
    const float* __restrict__ Wv,
    const float* __restrict__ sinT,   // [S, HD/2] flattened
    const float* __restrict__ cosT)
{
    __shared__ float As[BK][BM + 4];
    __shared__ float Bs[BK][BN + 4];

    const int which = blockIdx.z;
    const float* W = (which == 0) ? Wq : (which == 1 ? Wk : Wv);
    float* Out     = (which == 0) ? g_Q : (which == 1 ? g_K : g_V);

    const int bm = blockIdx.y * BM;
    const int bn = blockIdx.x * BN;
    const int tid = threadIdx.x;
    const int tx = tid & 15;       // col group 0..15  -> cols tx*8..+7
    const int ty = tid >> 4;       // row group 0..15  -> rows ty*8..+7

    // load indices
    const int ar = tid >> 2;         // 0..63 (A rows ar, ar+64)
    const int ac = (tid & 3) * 4;    // 0,4,8,12
    const int br = tid >> 4;         // 0..15
    const int bc = (tid & 15) * 4;   // 0..60 (B cols bc, bc+64)

    float acc[8][8];
    #pragma unroll
    for (int i = 0; i < 8; i++)
        #pragma unroll
        for (int j = 0; j < 8; j++) acc[i][j] = 0.f;

    for (int k0 = 0; k0 < D_; k0 += BK) {
        float4 a0 = *(const float4*)&X[(size_t)(bm + ar)      * D_ + k0 + ac];
        float4 a1 = *(const float4*)&X[(size_t)(bm + ar + 64) * D_ + k0 + ac];
        As[ac + 0][ar] = a0.x; As[ac + 1][ar] = a0.y;
        As[ac + 2][ar] = a0.z; As[ac + 3][ar] = a0.w;
        As[ac + 0][ar + 64] = a1.x; As[ac + 1][ar + 64] = a1.y;
        As[ac + 2][ar + 64] = a1.z; As[ac + 3][ar + 64] = a1.w;

        float4 b0 = *(const float4*)&W[(size_t)(k0 + br) * D_ + bn + bc];
        float4 b1 = *(const float4*)&W[(size_t)(k0 + br) * D_ + bn + bc + 64];
        *(float4*)&Bs[br][bc]      = b0;
        *(float4*)&Bs[br][bc + 64] = b1;
        __syncthreads();

        #pragma unroll
        for (int k = 0; k < BK; k++) {
            float a[8], b[8];
            *(float4*)&a[0] = *(const float4*)&As[k][ty * 8];
            *(float4*)&a[4] = *(const float4*)&As[k][ty * 8 + 4];
            *(float4*)&b[0] = *(const float4*)&Bs[k][tx * 8];
            *(float4*)&b[4] = *(const float4*)&Bs[k][tx * 8 + 4];
            #pragma unroll
            for (int i = 0; i < 8; i++)
                #pragma unroll
                for (int j = 0; j < 8; j++)
                    acc[i][j] += a[i] * b[j];
        }
        __syncthreads();
    }

    // Epilogue: RoPE + scatter into [B,H,S,HD]
    #pragma unroll
    for (int i = 0; i < 8; i++) {
        const int row = bm + ty * 8 + i;
        const int bb = row >> 11;      // / 2048
        const int ss = row & 2047;
        #pragma unroll
        for (int j = 0; j < 8; j += 2) {
            const int c = bn + tx * 8 + j;
            const int h = c >> 6;
            const int d = c & 63;
            const int p = d >> 1;
            const float sn = sinT[ss * (HD_ / 2) + p];
            const float cs = cosT[ss * (HD_ / 2) + p];
            const float e = acc[i][j];
            const float o = acc[i][j + 1];
            const size_t ob = ((size_t)(bb * H_ + h) * S_ + ss) * HD_ + d;
            Out[ob]     = e * cs - o * sn;
            Out[ob + 1] = o * cs + e * sn;
        }
    }
}

// ---------------------------------------------------------------------------
// Kernel 2: flash attention per (b,h). BQ=64 queries per block, loop over
// K/V in 64-row tiles, online softmax. 256 threads, 4x4 score micro-tile.
// Dynamic smem: Qs/Ks (transposed [hd][idx]), Vs [k][hd], Ps [q][k].
// ---------------------------------------------------------------------------
#define BQ  64
#define BKT 64
#define STRD (HD_ + 4)    // 68 floats/row: keeps 16B alignment for float4

__global__ __launch_bounds__(256) void attn_kernel(float* __restrict__ Out)
{
    extern __shared__ float sm2[];
    float* Qs = sm2;                    // [HD][STRD] indexed [hd][q] (pre-scaled)
    float* Ks = Qs + 64 * STRD;         // [hd][k]
    float* Vs = Ks + 64 * STRD;         // [k][hd]
    float* Ps = Vs + 64 * STRD;         // [q][k]

    const int q0 = blockIdx.x * BQ;
    const int h  = blockIdx.y;
    const int b  = blockIdx.z;

    const float* Qg = g_Q + (size_t)(b * H_ + h) * S_ * HD_;
    const float* Kg = g_K + (size_t)(b * H_ + h) * S_ * HD_;
    const float* Vg = g_V + (size_t)(b * H_ + h) * S_ * HD_;

    const int tid = threadIdx.x;
    const int tx = tid & 15;   // score cols tx*4..+3 (and hd cols for O)
    const int ty = tid >> 4;   // score rows ty*4..+3

    const int lr = tid >> 4;         // 0..15 (load row base)
    const int lc = (tid & 15) * 4;   // 0..60 (load col, float4)

    // Load Q tile (transposed, pre-scaled by 1/sqrt(HD)=0.125)
    #pragma unroll
    for (int rr = 0; rr < 64; rr += 16) {
        float4 v = *(const float4*)&Qg[(size_t)(q0 + lr + rr) * HD_ + lc];
        Qs[(lc + 0) * STRD + lr + rr] = v.x * 0.125f;
        Qs[(lc + 1) * STRD + lr + rr] = v.y * 0.125f;
        Qs[(lc + 2) * STRD + lr + rr] = v.z * 0.125f;
        Qs[(lc + 3) * STRD + lr + rr] = v.w * 0.125f;
    }

    float m_i[4], l_i[4], o_acc[4][4];
    #pragma unroll
    for (int i = 0; i < 4; i++) {
        m_i[i] = -INFINITY; l_i[i] = 0.f;
        #pragma unroll
        for (int j = 0; j < 4; j++) o_acc[i][j] = 0.f;
    }
    __syncthreads();

    for (int kt = 0; kt < S_; kt += BKT) {
        // load K (transposed) + V (direct) tiles
        #pragma unroll
        for (int rr = 0; rr < 64; rr += 16) {
            float4 kv = *(const float4*)&Kg[(size_t)(kt + lr + rr) * HD_ + lc];
            Ks[(lc + 0) * STRD + lr + rr] = kv.x;
            Ks[(lc + 1) * STRD + lr + rr] = kv.y;
            Ks[(lc + 2) * STRD + lr + rr] = kv.z;
            Ks[(lc + 3) * STRD + lr + rr] = kv.w;
            float4 vv = *(const float4*)&Vg[(size_t)(kt + lr + rr) * HD_ + lc];
            *(float4*)&Vs[(lr + rr) * STRD + lc] = vv;
        }
        __syncthreads();

        // scores: sc[i][j] = sum_d Qs[d][ty*4+i] * Ks[d][tx*4+j]
        float sc[4][4];
        #pragma unroll
        for (int i = 0; i < 4; i++)
            #pragma unroll
            for (int j = 0; j < 4; j++) sc[i][j] = 0.f;

        #pragma unroll 8
        for (int d = 0; d < HD_; d++) {
            float4 qv = *(const float4*)&Qs[d * STRD + ty * 4];
            float4 kk = *(const float4*)&Ks[d * STRD + tx * 4];
            float aq[4] = {qv.x, qv.y, qv.z, qv.w};
            float bk[4] = {kk.x, kk.y, kk.z, kk.w};
            #pragma unroll
            for (int i = 0; i < 4; i++)
                #pragma unroll
                for (int j = 0; j < 4; j++)
                    sc[i][j] += aq[i] * bk[j];
        }

        // online softmax, row-wise over 16 tx lanes
        #pragma unroll
        for (int i = 0; i < 4; i++) {
            float mx = fmaxf(fmaxf(sc[i][0], sc[i][1]), fmaxf(sc[i][2], sc[i][3]));
            #pragma unroll
            for (int off = 8; off > 0; off >>= 1)
                mx = fmaxf(mx, __shfl_xor_sync(0xffffffffu, mx, off));
            const float mnew = fmaxf(m_i[i], mx);
            const float corr = __expf(m_i[i] - mnew);
            m_i[i] = mnew;

            float4 p;
            p.x = __expf(sc[i][0] - mnew);
            p.y = __expf(sc[i][1] - mnew);
            p.z = __expf(sc[i][2] - mnew);
            p.w = __expf(sc[i][3] - mnew);
            float rs = p.x + p.y + p.z + p.w;
            #pragma unroll
            for (int off = 8; off > 0; off >>= 1)
                rs += __shfl_xor_sync(0xffffffffu, rs, off);
            l_i[i] = l_i[i] * corr + rs;
            #pragma unroll
            for (int j = 0; j < 4; j++) o_acc[i][j] *= corr;
            *(float4*)&Ps[(ty * 4 + i) * STRD + tx * 4] = p;
        }
        __syncthreads();

        // O += P @ V   (k unrolled by 4, float4 smem reads)
        #pragma unroll 4
        for (int k4 = 0; k4 < BKT; k4 += 4) {
            float4 v0 = *(const float4*)&Vs[(k4 + 0) * STRD + tx * 4];
            float4 v1 = *(const float4*)&Vs[(k4 + 1) * STRD + tx * 4];
            float4 v2 = *(const float4*)&Vs[(k4 + 2) * STRD + tx * 4];
            float4 v3 = *(const float4*)&Vs[(k4 + 3) * STRD + tx * 4];
            #pragma unroll
            for (int i = 0; i < 4; i++) {
                float4 pp = *(const float4*)&Ps[(ty * 4 + i) * STRD + k4];
                o_acc[i][0] += pp.x * v0.x + pp.y * v1.x + pp.z * v2.x + pp.w * v3.x;
                o_acc[i][1] += pp.x * v0.y + pp.y * v1.y + pp.z * v2.y + pp.w * v3.y;
                o_acc[i][2] += pp.x * v0.z + pp.y * v1.z + pp.z * v2.z + pp.w * v3.z;
                o_acc[i][3] += pp.x * v0.w + pp.y * v1.w + pp.z * v2.w + pp.w * v3.w;
            }
        }
        __syncthreads();
    }

    // epilogue: out[b][q][h*64 + hd] = o / l
    #pragma unroll
    for (int i = 0; i < 4; i++) {
        const int q = q0 + ty * 4 + i;
        const float inv = 1.f / l_i[i];
        float4 r;
        r.x = o_acc[i][0] * inv;
        r.y = o_acc[i][1] * inv;
        r.z = o_acc[i][2] * inv;
        r.w = o_acc[i][3] * inv;
        *(float4*)&Out[((size_t)b * S_ + q) * D_ + h * HD_ + tx * 4] = r;
    }
}

// ---------------------------------------------------------------------------
extern "C" void kernel_launch(void* const* d_in, const int* in_sizes, int n_in,
                              void* d_out, int out_size)
{
    const float* X  = (const float*)d_in[0];
    const float* Wq = (const float*)d_in[1];
    const float* Wk = (const float*)d_in[2];
    const float* Wv = (const float*)d_in[3];
    const float* sn = (const float*)d_in[4];
    const float* cs = (const float*)d_in[5];
    float* out = (float*)d_out;

    dim3 g1(D_ / BN, M_ / BM, 3);   // (8, 32, 3)
    qkv_rope_kernel<<<g1, 256>>>(X, Wq, Wk, Wv, sn, cs);

    const int smem2 = 4 * 64 * STRD * (int)sizeof(float);  // 69632 B
    cudaFuncSetAttribute(attn_kernel, cudaFuncAttributeMaxDynamicSharedMemorySize, smem2);
    dim3 g2(S_ / BQ, H_, B_);       // (32, 16, 2)
    attn_kernel<<<g2, 256, smem2>>>(out);
}

// round 3
// speedup vs baseline: 1.3329x; 1.3329x over previous
#include <cuda_runtime.h>
#include <cuda_bf16.h>
#include <math.h>
#include <stdint.h>

#define B_  2
#define S_  2048
#define D_  1024
#define H_  16
#define HD_ 64
#define M_  (B_*S_)   // 4096

// Scratch for rotated Q/K/V in [B,H,S,HD] layout (fp32)
__device__ float g_Q[B_*H_*S_*HD_];
__device__ float g_K[B_*H_*S_*HD_];
__device__ float g_V[B_*H_*S_*HD_];

// ===========================================================================
// helpers
// ===========================================================================
__device__ __forceinline__ uint32_t smem_u32(const void* p) {
    uint32_t a;
    asm("{ .reg .u64 t; cvta.to.shared.u64 t, %1; cvt.u32.u64 %0, t; }" : "=r"(a) : "l"(p));
    return a;
}
// SW128 swizzle for 128-byte rows (row-major byte offset in)
#define SWZ(off) ((off) ^ (((off) >> 3) & 0x70))

__device__ __forceinline__ void ldm_x4(uint32_t& r0, uint32_t& r1, uint32_t& r2, uint32_t& r3, uint32_t a) {
    asm volatile("ldmatrix.sync.aligned.m8n8.x4.shared.b16 {%0,%1,%2,%3}, [%4];"
                 : "=r"(r0), "=r"(r1), "=r"(r2), "=r"(r3) : "r"(a));
}
__device__ __forceinline__ void ldm_x2(uint32_t& r0, uint32_t& r1, uint32_t a) {
    asm volatile("ldmatrix.sync.aligned.m8n8.x2.shared.b16 {%0,%1}, [%2];"
                 : "=r"(r0), "=r"(r1) : "r"(a));
}
__device__ __forceinline__ void mma16816(float* c, const uint32_t* a, uint32_t b0, uint32_t b1) {
    asm volatile(
        "mma.sync.aligned.m16n8k16.row.col.f32.bf16.bf16.f32 "
        "{%0,%1,%2,%3}, {%4,%5,%6,%7}, {%8,%9}, {%0,%1,%2,%3};"
        : "+f"(c[0]), "+f"(c[1]), "+f"(c[2]), "+f"(c[3])
        : "r"(a[0]), "r"(a[1]), "r"(a[2]), "r"(a[3]), "r"(b0), "r"(b1));
}
// split x into bf16 hi/lo
__device__ __forceinline__ void split_bf16(float x, __nv_bfloat16& h, __nv_bfloat16& l) {
    h = __float2bfloat16(x);
    l = __float2bfloat16(x - __bfloat162float(h));
}
__device__ __forceinline__ uint32_t pack2(__nv_bfloat16 e0, __nv_bfloat16 e1) {
    __nv_bfloat162 t(e0, e1);           // .x = e0 (low = even k), .y = e1
    return *reinterpret_cast<uint32_t*>(&t);
}

// ===========================================================================
// Kernel 1: QKV GEMM (split-bf16 HMMA) + RoPE epilogue
//   C = X(4096x1024) @ W(1024x1024); tile 128x128, BK=64, 8 warps (32x64 each)
// smem planes (bf16, SW128, 128B rows of 64 elems): Ah Al Bh(=Wt) Bl, 16KB each
// ===========================================================================
#define QKV_SMEM (4 * 16384)

__global__ __launch_bounds__(256)
void qkv_hmma_kernel(const float* __restrict__ X,
                     const float* __restrict__ Wq,
                     const float* __restrict__ Wk,
                     const float* __restrict__ Wv,
                     const float* __restrict__ sinT,
                     const float* __restrict__ cosT)
{
    extern __shared__ char smem[];
    char* Ah = smem;
    char* Al = smem + 16384;
    char* Bh = smem + 32768;
    char* Bl = smem + 49152;
    const uint32_t sAh = smem_u32(Ah), sAl = smem_u32(Al);
    const uint32_t sBh = smem_u32(Bh), sBl = smem_u32(Bl);

    const int tid = threadIdx.x;
    const int wid = tid >> 5;
    const int lane = tid & 31;
    const int wm = (wid >> 1) * 32;    // warp m offset (0,32,64,96)
    const int wn = (wid & 1) * 64;     // warp n offset (0,64)

    const int which = blockIdx.z;
    const float* W = (which == 0) ? Wq : (which == 1 ? Wk : Wv);
    float* Out     = (which == 0) ? g_Q : (which == 1 ? g_K : g_V);
    const int bm = blockIdx.y * 128;
    const int bn = blockIdx.x * 128;

    float acc[2][8][4];
    #pragma unroll
    for (int i = 0; i < 2; i++)
        #pragma unroll
        for (int j = 0; j < 8; j++)
            #pragma unroll
            for (int k = 0; k < 4; k++) acc[i][j][k] = 0.f;

    for (int ch = 0; ch < 16; ch++) {
        // ---- load A chunk X[bm:+128][ch*64:+64] ----
        #pragma unroll
        for (int it = 0; it < 8; it++) {
            const int idx = it * 256 + tid;       // 2048 float4
            const int m  = idx >> 4;
            const int c4 = (idx & 15) << 2;
            float4 v = *(const float4*)&X[(size_t)(bm + m) * D_ + ch * 64 + c4];
            __nv_bfloat16 h0, l0, h1, l1, h2, l2, h3, l3;
            split_bf16(v.x, h0, l0); split_bf16(v.y, h1, l1);
            split_bf16(v.z, h2, l2); split_bf16(v.w, h3, l3);
            const uint32_t off = SWZ((uint32_t)(m * 128 + c4 * 2));
            *(uint32_t*)(Ah + off)     = pack2(h0, h1);
            *(uint32_t*)(Ah + off + 4) = pack2(h2, h3);
            *(uint32_t*)(Al + off)     = pack2(l0, l1);
            *(uint32_t*)(Al + off + 4) = pack2(l2, l3);
        }
        // ---- load B chunk W[ch*64:+64][bn:+128] -> Bt[n][k] ----
        #pragma unroll
        for (int it = 0; it < 8; it++) {
            const int idx = it * 256 + tid;
            const int kk = idx >> 5;              // 0..63
            const int n4 = (idx & 31) << 2;       // 0..124
            float4 v = *(const float4*)&W[(size_t)(ch * 64 + kk) * D_ + bn + n4];
            const float vs[4] = {v.x, v.y, v.z, v.w};
            #pragma unroll
            for (int e = 0; e < 4; e++) {
                __nv_bfloat16 h, l;
                split_bf16(vs[e], h, l);
                const uint32_t off = SWZ((uint32_t)((n4 + e) * 128 + kk * 2));
                *(__nv_bfloat16*)(Bh + off) = h;
                *(__nv_bfloat16*)(Bl + off) = l;
            }
        }
        __syncthreads();

        // ---- MMA on the chunk ----
        #pragma unroll
        for (int ks = 0; ks < 4; ks++) {
            const int koff = ks * 32;
            uint32_t ah[2][4], al[2][4];
            #pragma unroll
            for (int mt = 0; mt < 2; mt++) {
                const int row = wm + mt * 16 + (lane & 15);
                const uint32_t byt = (uint32_t)(row * 128 + koff + ((lane >> 4) << 4));
                ldm_x4(ah[mt][0], ah[mt][1], ah[mt][2], ah[mt][3], sAh + SWZ(byt));
                ldm_x4(al[mt][0], al[mt][1], al[mt][2], al[mt][3], sAl + SWZ(byt));
            }
            #pragma unroll
            for (int nt = 0; nt < 8; nt++) {
                const int row = wn + nt * 8 + (lane & 7);
                const uint32_t byt = (uint32_t)(row * 128 + koff + (((lane >> 3) & 1) << 4));
                uint32_t bh0, bh1, bl0, bl1;
                ldm_x2(bh0, bh1, sBh + SWZ(byt));
                ldm_x2(bl0, bl1, sBl + SWZ(byt));
                #pragma unroll
                for (int mt = 0; mt < 2; mt++) {
                    mma16816(acc[mt][nt], ah[mt], bh0, bh1);
                    mma16816(acc[mt][nt], ah[mt], bl0, bl1);
                    mma16816(acc[mt][nt], al[mt], bh0, bh1);
                }
            }
        }
        __syncthreads();
    }

    // ---- epilogue: RoPE + scatter, fragment pairs (2q,2q+1) are RoPE pairs ----
    const int g = lane >> 2;
    const int q2 = (lane & 3) * 2;
    #pragma unroll
    for (int mt = 0; mt < 2; mt++) {
        #pragma unroll
        for (int rr = 0; rr < 2; rr++) {            // row g / g+8
            const int row = bm + wm + mt * 16 + g + rr * 8;
            const int bb = row >> 11;
            const int ss = row & 2047;
            #pragma unroll
            for (int nt = 0; nt < 8; nt++) {
                const int c = bn + wn + nt * 8 + q2;
                const int h = c >> 6;
                const int d = c & 63;
                const float sn = sinT[ss * (HD_ / 2) + (d >> 1)];
                const float cs = cosT[ss * (HD_ / 2) + (d >> 1)];
                const float e = acc[mt][nt][rr * 2 + 0];
                const float o = acc[mt][nt][rr * 2 + 1];
                float2 w;
                w.x = e * cs - o * sn;
                w.y = o * cs + e * sn;
                *(float2*)&Out[((size_t)(bb * H_ + h) * S_ + ss) * HD_ + d] = w;
            }
        }
    }
}

// ===========================================================================
// Kernel 2: flash attention with HMMA.
//   Block: 128 queries, 8 warps x 16 rows (warp-exclusive rows -> warp-local
//   softmax). kt tiles of 64. P stays in registers (D-frag == A-frag layout).
// smem: Qh Ql [128][64] (16KB ea), Kh Kl [64][64] (8KB ea), Vth Vtl [64][64]
// ===========================================================================
#define ATT_SMEM (16384*2 + 8192*4)

__global__ __launch_bounds__(256)
void attn_hmma_kernel(float* __restrict__ Out)
{
    extern __shared__ char smem[];
    char* Qh = smem;
    char* Ql = smem + 16384;
    char* Kh = smem + 32768;
    char* Kl = smem + 40960;
    char* Vh = smem + 49152;
    char* Vl = smem + 57344;
    const uint32_t sQh = smem_u32(Qh), sQl = smem_u32(Ql);
    const uint32_t sKh = smem_u32(Kh), sKl = smem_u32(Kl);
    const uint32_t sVh = smem_u32(Vh), sVl = smem_u32(Vl);

    const int tid = threadIdx.x;
    const int wid = tid >> 5;
    const int lane = tid & 31;
    const int g = lane >> 2;
    const int q2 = (lane & 3) * 2;

    const int q0 = blockIdx.x * 128;
    const int h  = blockIdx.y;
    const int b  = blockIdx.z;
    const float* Qg = g_Q + (size_t)(b * H_ + h) * S_ * HD_;
    const float* Kg = g_K + (size_t)(b * H_ + h) * S_ * HD_;
    const float* Vg = g_V + (size_t)(b * H_ + h) * S_ * HD_;

    // ---- load Q tile (scaled by 0.125), split, swizzle ----
    #pragma unroll
    for (int it = 0; it < 8; it++) {
        const int idx = it * 256 + tid;
        const int m  = idx >> 4;
        const int c4 = (idx & 15) << 2;
        float4 v = *(const float4*)&Qg[(size_t)(q0 + m) * HD_ + c4];
        __nv_bfloat16 h0, l0, h1, l1, h2, l2, h3, l3;
        split_bf16(v.x * 0.125f, h0, l0); split_bf16(v.y * 0.125f, h1, l1);
        split_bf16(v.z * 0.125f, h2, l2); split_bf16(v.w * 0.125f, h3, l3);
        const uint32_t off = SWZ((uint32_t)(m * 128 + c4 * 2));
        *(uint32_t*)(Qh + off)     = pack2(h0, h1);
        *(uint32_t*)(Qh + off + 4) = pack2(h2, h3);
        *(uint32_t*)(Ql + off)     = pack2(l0, l1);
        *(uint32_t*)(Ql + off + 4) = pack2(l2, l3);
    }
    __syncthreads();

    // ---- Q fragments in registers (held for whole kernel) ----
    uint32_t qh[4][4], ql[4][4];
    #pragma unroll
    for (int ks = 0; ks < 4; ks++) {
        const int row = wid * 16 + (lane & 15);
        const uint32_t byt = (uint32_t)(row * 128 + ks * 32 + ((lane >> 4) << 4));
        ldm_x4(qh[ks][0], qh[ks][1], qh[ks][2], qh[ks][3], sQh + SWZ(byt));
        ldm_x4(ql[ks][0], ql[ks][1], ql[ks][2], ql[ks][3], sQl + SWZ(byt));
    }

    float m_[2] = {-INFINITY, -INFINITY};
    float l_[2] = {0.f, 0.f};
    float o_acc[8][4];
    #pragma unroll
    for (int i = 0; i < 8; i++)
        #pragma unroll
        for (int j = 0; j < 4; j++) o_acc[i][j] = 0.f;

    for (int kt = 0; kt < S_ / 64; kt++) {
        // ---- load K tile [64][64] and V tile (transposed) ----
        #pragma unroll
        for (int it = 0; it < 4; it++) {
            const int idx = it * 256 + tid;       // 1024 float4
            const int r  = idx >> 4;              // 0..63
            const int c4 = (idx & 15) << 2;
            float4 kv = *(const float4*)&Kg[(size_t)(kt * 64 + r) * HD_ + c4];
            __nv_bfloat16 h0, l0, h1, l1, h2, l2, h3, l3;
            split_bf16(kv.x, h0, l0); split_bf16(kv.y, h1, l1);
            split_bf16(kv.z, h2, l2); split_bf16(kv.w, h3, l3);
            const uint32_t off = SWZ((uint32_t)(r * 128 + c4 * 2));
            *(uint32_t*)(Kh + off)     = pack2(h0, h1);
            *(uint32_t*)(Kh + off + 4) = pack2(h2, h3);
            *(uint32_t*)(Kl + off)     = pack2(l0, l1);
            *(uint32_t*)(Kl + off + 4) = pack2(l2, l3);

            float4 vv = *(const float4*)&Vg[(size_t)(kt * 64 + r) * HD_ + c4];
            const float vs[4] = {vv.x, vv.y, vv.z, vv.w};
            #pragma unroll
            for (int e = 0; e < 4; e++) {
                __nv_bfloat16 vh, vl;
                split_bf16(vs[e], vh, vl);
                const uint32_t ot = SWZ((uint32_t)((c4 + e) * 128 + r * 2));
                *(__nv_bfloat16*)(Vh + ot) = vh;
                *(__nv_bfloat16*)(Vl + ot) = vl;
            }
        }
        __syncthreads();

        // ---- scores S = Q K^T ----
        float sc[8][4];
        #pragma unroll
        for (int i = 0; i < 8; i++)
            #pragma unroll
            for (int j = 0; j < 4; j++) sc[i][j] = 0.f;

        #pragma unroll
        for (int ks = 0; ks < 4; ks++) {
            #pragma unroll
            for (int nt = 0; nt < 8; nt++) {
                const int row = nt * 8 + (lane & 7);
                const uint32_t byt = (uint32_t)(row * 128 + ks * 32 + (((lane >> 3) & 1) << 4));
                uint32_t bh0, bh1, bl0, bl1;
                ldm_x2(bh0, bh1, sKh + SWZ(byt));
                ldm_x2(bl0, bl1, sKl + SWZ(byt));
                mma16816(sc[nt], qh[ks], bh0, bh1);
                mma16816(sc[nt], qh[ks], bl0, bl1);
                mma16816(sc[nt], ql[ks], bh0, bh1);
            }
        }

        // ---- online softmax (warp-local, quad reduce over lanes xor 1,2) ----
        #pragma unroll
        for (int tr = 0; tr < 2; tr++) {
            float tmax = -INFINITY;
            #pragma unroll
            for (int nt = 0; nt < 8; nt++)
                tmax = fmaxf(tmax, fmaxf(sc[nt][tr * 2], sc[nt][tr * 2 + 1]));
            tmax = fmaxf(tmax, __shfl_xor_sync(0xffffffffu, tmax, 1));
            tmax = fmaxf(tmax, __shfl_xor_sync(0xffffffffu, tmax, 2));
            const float mnew = fmaxf(m_[tr], tmax);
            const float corr = __expf(m_[tr] - mnew);
            m_[tr] = mnew;
            float rs = 0.f;
            #pragma unroll
            for (int nt = 0; nt < 8; nt++) {
                const float p0 = __expf(sc[nt][tr * 2]     - mnew);
                const float p1 = __expf(sc[nt][tr * 2 + 1] - mnew);
                sc[nt][tr * 2]     = p0;
                sc[nt][tr * 2 + 1] = p1;
                rs += p0 + p1;
            }
            rs += __shfl_xor_sync(0xffffffffu, rs, 1);
            rs += __shfl_xor_sync(0xffffffffu, rs, 2);
            l_[tr] = l_[tr] * corr + rs;
            #pragma unroll
            for (int dt = 0; dt < 8; dt++) {
                o_acc[dt][tr * 2]     *= corr;
                o_acc[dt][tr * 2 + 1] *= corr;
            }
        }

        // ---- O += P V : P fragments built in registers from score frags ----
        #pragma unroll
        for (int ks2 = 0; ks2 < 4; ks2++) {
            uint32_t aH[4], aL[4];
            #pragma unroll
            for (int half = 0; half < 2; half++) {
                const int nt = 2 * ks2 + half;
                __nv_bfloat16 h0, l0, h1, l1, h2, l2, h3, l3;
                split_bf16(sc[nt][0], h0, l0); split_bf16(sc[nt][1], h1, l1);
                split_bf16(sc[nt][2], h2, l2); split_bf16(sc[nt][3], h3, l3);
                aH[half * 2 + 0] = pack2(h0, h1);   // row g
                aH[half * 2 + 1] = pack2(h2, h3);   // row g+8
                aL[half * 2 + 0] = pack2(l0, l1);
                aL[half * 2 + 1] = pack2(l2, l3);
            }
            // NOTE: A-frag reg order is {rowg k0-7, rowg+8 k0-7, rowg k8-15, rowg+8 k8-15}
            uint32_t aHf[4] = {aH[0], aH[1], aH[2], aH[3]};
            uint32_t aLf[4] = {aL[0], aL[1], aL[2], aL[3]};
            #pragma unroll
            for (int dt = 0; dt < 8; dt++) {
                const int row = dt * 8 + (lane & 7);
                const uint32_t byt = (uint32_t)(row * 128 + ks2 * 32 + (((lane >> 3) & 1) << 4));
                uint32_t bh0, bh1, bl0, bl1;
                ldm_x2(bh0, bh1, sVh + SWZ(byt));
                ldm_x2(bl0, bl1, sVl + SWZ(byt));
                mma16816(o_acc[dt], aHf, bh0, bh1);
                mma16816(o_acc[dt], aHf, bl0, bl1);
                mma16816(o_acc[dt], aLf, bh0, bh1);
            }
        }
        __syncthreads();
    }

    // ---- epilogue ----
    #pragma unroll
    for (int tr = 0; tr < 2; tr++) {
        const int qrow = q0 + wid * 16 + g + tr * 8;
        const float inv = 1.f / l_[tr];
        #pragma unroll
        for (int dt = 0; dt < 8; dt++) {
            float2 w;
            w.x = o_acc[dt][tr * 2]     * inv;
            w.y = o_acc[dt][tr * 2 + 1] * inv;
            *(float2*)&Out[((size_t)b * S_ + qrow) * D_ + h * HD_ + dt * 8 + q2] = w;
        }
    }
}

// ---------------------------------------------------------------------------
extern "C" void kernel_launch(void* const* d_in, const int* in_sizes, int n_in,
                              void* d_out, int out_size)
{
    const float* X  = (const float*)d_in[0];
    const float* Wq = (const float*)d_in[1];
    const float* Wk = (const float*)d_in[2];
    const float* Wv = (const float*)d_in[3];
    const float* sn = (const float*)d_in[4];
    const float* cs = (const float*)d_in[5];
    float* out = (float*)d_out;

    cudaFuncSetAttribute(qkv_hmma_kernel, cudaFuncAttributeMaxDynamicSharedMemorySize, QKV_SMEM);
    dim3 g1(D_ / 128, M_ / 128, 3);   // (8, 32, 3)
    qkv_hmma_kernel<<<g1, 256, QKV_SMEM>>>(X, Wq, Wk, Wv, sn, cs);

    cudaFuncSetAttribute(attn_hmma_kernel, cudaFuncAttributeMaxDynamicSharedMemorySize, ATT_SMEM);
    dim3 g2(S_ / 128, H_, B_);        // (16, 16, 2)
    attn_hmma_kernel<<<g2, 256, ATT_SMEM>>>(out);
}

// round 4
// speedup vs baseline: 2.7382x; 2.0543x over previous
#include <cuda_runtime.h>
#include <cuda_bf16.h>
#include <math.h>
#include <stdint.h>

#define B_  2
#define S_  2048
#define D_  1024
#define H_  16
#define HD_ 64
#define M_  (B_*S_)   // 4096

// Pre-split bf16 planes (prep kernels)
__device__ __nv_bfloat16 g_Xh[M_*D_], g_Xl[M_*D_];               // X  [m][k]
__device__ __nv_bfloat16 g_Wth[3*D_*D_], g_Wtl[3*D_*D_];         // Wt [n][k] x3
// Rotated Q/K/V bf16 hi/lo planes, [B,H,S,HD] (Q pre-scaled by 0.125)
__device__ __nv_bfloat16 g_Qh[B_*H_*S_*HD_], g_Ql[B_*H_*S_*HD_];
__device__ __nv_bfloat16 g_Kh[B_*H_*S_*HD_], g_Kl[B_*H_*S_*HD_];
__device__ __nv_bfloat16 g_Vh[B_*H_*S_*HD_], g_Vl[B_*H_*S_*HD_];

// ===========================================================================
// helpers
// ===========================================================================
__device__ __forceinline__ uint32_t smem_u32(const void* p) {
    uint32_t a;
    asm("{ .reg .u64 t; cvta.to.shared.u64 t, %1; cvt.u32.u64 %0, t; }" : "=r"(a) : "l"(p));
    return a;
}
#define SWZ(off) ((off) ^ (((off) >> 3) & 0x70))

__device__ __forceinline__ void cpa16(uint32_t dst, const void* src) {
    asm volatile("cp.async.cg.shared.global [%0], [%1], 16;" :: "r"(dst), "l"(src));
}
#define CPA_COMMIT() asm volatile("cp.async.commit_group;" ::: "memory")
#define CPA_WAIT(n)  asm volatile("cp.async.wait_group %0;" :: "n"(n) : "memory")

__device__ __forceinline__ void ldm_x4(uint32_t& r0, uint32_t& r1, uint32_t& r2, uint32_t& r3, uint32_t a) {
    asm volatile("ldmatrix.sync.aligned.m8n8.x4.shared.b16 {%0,%1,%2,%3}, [%4];"
                 : "=r"(r0), "=r"(r1), "=r"(r2), "=r"(r3) : "r"(a));
}
__device__ __forceinline__ void ldm_x2(uint32_t& r0, uint32_t& r1, uint32_t a) {
    asm volatile("ldmatrix.sync.aligned.m8n8.x2.shared.b16 {%0,%1}, [%2];"
                 : "=r"(r0), "=r"(r1) : "r"(a));
}
__device__ __forceinline__ void ldm_x2t(uint32_t& r0, uint32_t& r1, uint32_t a) {
    asm volatile("ldmatrix.sync.aligned.m8n8.x2.trans.shared.b16 {%0,%1}, [%2];"
                 : "=r"(r0), "=r"(r1) : "r"(a));
}
__device__ __forceinline__ void mma16816(float* c, const uint32_t* a, uint32_t b0, uint32_t b1) {
    asm volatile(
        "mma.sync.aligned.m16n8k16.row.col.f32.bf16.bf16.f32 "
        "{%0,%1,%2,%3}, {%4,%5,%6,%7}, {%8,%9}, {%0,%1,%2,%3};"
        : "+f"(c[0]), "+f"(c[1]), "+f"(c[2]), "+f"(c[3])
        : "r"(a[0]), "r"(a[1]), "r"(a[2]), "r"(a[3]), "r"(b0), "r"(b1));
}
__device__ __forceinline__ void split_bf16(float x, __nv_bfloat16& h, __nv_bfloat16& l) {
    h = __float2bfloat16(x);
    l = __float2bfloat16(x - __bfloat162float(h));
}
__device__ __forceinline__ uint32_t pack2(__nv_bfloat16 e0, __nv_bfloat16 e1) {
    __nv_bfloat162 t(e0, e1);
    return *reinterpret_cast<uint32_t*>(&t);
}

// ===========================================================================
// Prep 1: split X into bf16 hi/lo planes (same [m][k] layout)
// ===========================================================================
__global__ __launch_bounds__(256) void split_x_kernel(const float* __restrict__ X)
{
    const int i = blockIdx.x * 256 + threadIdx.x;     // float4 index
    float4 v = ((const float4*)X)[i];
    __nv_bfloat16 h0, l0, h1, l1, h2, l2, h3, l3;
    split_bf16(v.x, h0, l0); split_bf16(v.y, h1, l1);
    split_bf16(v.z, h2, l2); split_bf16(v.w, h3, l3);
    ((__nv_bfloat162*)g_Xh)[i*2]   = __nv_bfloat162(h0, h1);
    ((__nv_bfloat162*)g_Xh)[i*2+1] = __nv_bfloat162(h2, h3);
    ((__nv_bfloat162*)g_Xl)[i*2]   = __nv_bfloat162(l0, l1);
    ((__nv_bfloat162*)g_Xl)[i*2+1] = __nv_bfloat162(l2, l3);
}

// ===========================================================================
// Prep 2: transpose + split W -> Wt[n][k] hi/lo. 64x64 tiles via smem.
// ===========================================================================
__global__ __launch_bounds__(256) void transw_kernel(
    const float* __restrict__ Wq, const float* __restrict__ Wk, const float* __restrict__ Wv)
{
    __shared__ float tile[64][65];
    const int w = blockIdx.z;
    const float* W = (w == 0) ? Wq : (w == 1 ? Wk : Wv);
    const int k0 = blockIdx.x * 64;
    const int n0 = blockIdx.y * 64;
    const int tid = threadIdx.x;

    #pragma unroll
    for (int it = 0; it < 4; it++) {
        const int idx = it * 256 + tid;
        const int r = idx >> 4, c4 = (idx & 15) << 2;
        float4 v = *(const float4*)&W[(size_t)(k0 + r) * D_ + n0 + c4];
        tile[r][c4] = v.x; tile[r][c4+1] = v.y; tile[r][c4+2] = v.z; tile[r][c4+3] = v.w;
    }
    __syncthreads();
    __nv_bfloat16* Oh = g_Wth + (size_t)w * D_ * D_;
    __nv_bfloat16* Ol = g_Wtl + (size_t)w * D_ * D_;
    #pragma unroll
    for (int it = 0; it < 4; it++) {
        const int idx = it * 256 + tid;
        const int rn = idx >> 4, kc4 = (idx & 15) << 2;
        __nv_bfloat16 h[4], l[4];
        #pragma unroll
        for (int e = 0; e < 4; e++) split_bf16(tile[kc4 + e][rn], h[e], l[e]);
        const size_t o = (size_t)(n0 + rn) * D_ + k0 + kc4;
        *(__nv_bfloat162*)&Oh[o]   = __nv_bfloat162(h[0], h[1]);
        *(__nv_bfloat162*)&Oh[o+2] = __nv_bfloat162(h[2], h[3]);
        *(__nv_bfloat162*)&Ol[o]   = __nv_bfloat162(l[0], l[1]);
        *(__nv_bfloat162*)&Ol[o+2] = __nv_bfloat162(l[2], l[3]);
    }
}

// ===========================================================================
// Kernel 1: QKV GEMM, cp.async 3-stage pipeline + RoPE epilogue.
//   Tile 128x128, BK=64 chunks x16. Stage = Ah Al Bh Bl (16KB each) = 64KB.
// ===========================================================================
#define QKV_SMEM (3 * 65536)

__global__ __launch_bounds__(256)
void qkv_hmma_kernel(const float* __restrict__ sinT, const float* __restrict__ cosT)
{
    extern __shared__ char smem[];
    const uint32_t sbase = smem_u32(smem);
    const int tid = threadIdx.x;
    const int wid = tid >> 5;
    const int lane = tid & 31;
    const int wm = (wid >> 1) * 32;
    const int wn = (wid & 1) * 64;

    const int which = blockIdx.z;
    const int bm = blockIdx.y * 128;
    const int bn = blockIdx.x * 128;
    const __nv_bfloat16* Bth = g_Wth + (size_t)which * D_ * D_;
    const __nv_bfloat16* Btl = g_Wtl + (size_t)which * D_ * D_;
    __nv_bfloat16* OutH = (which == 0) ? g_Qh : (which == 1 ? g_Kh : g_Vh);
    __nv_bfloat16* OutL = (which == 0) ? g_Ql : (which == 1 ? g_Kl : g_Vl);
    const float qscale = (which == 0) ? 0.125f : 1.0f;

    // issue one chunk into a stage (4 planes x 1024 cp.async of 16B)
    auto issue = [&](int ch, int st) {
        const uint32_t sb = sbase + st * 65536;
        const __nv_bfloat16* planes[4] = {g_Xh, g_Xl, Bth, Btl};
        #pragma unroll
        for (int p = 0; p < 4; p++) {
            const int rbase = (p < 2) ? bm : bn;
            #pragma unroll
            for (int it = 0; it < 4; it++) {
                const int idx = it * 256 + tid;    // 1024 per plane
                const int row = idx >> 3, ck = idx & 7;
                const void* src = planes[p] + (size_t)(rbase + row) * D_ + ch * 64 + ck * 8;
                cpa16(sb + p * 16384 + SWZ((uint32_t)(row * 128 + ck * 16)), src);
            }
        }
        CPA_COMMIT();
    };

    float acc[2][8][4];
    #pragma unroll
    for (int i = 0; i < 2; i++)
        #pragma unroll
        for (int j = 0; j < 8; j++)
            #pragma unroll
            for (int k = 0; k < 4; k++) acc[i][j][k] = 0.f;

    issue(0, 0); issue(1, 1); issue(2, 2);

    for (int ch = 0; ch < 16; ch++) {
        if (ch < 14)      { CPA_WAIT(2); }
        else if (ch == 14){ CPA_WAIT(1); }
        else              { CPA_WAIT(0); }
        __syncthreads();

        const int st = ch % 3;
        const uint32_t sAh = sbase + st * 65536;
        const uint32_t sAl = sAh + 16384;
        const uint32_t sBh = sAh + 32768;
        const uint32_t sBl = sAh + 49152;

        #pragma unroll
        for (int ks = 0; ks < 4; ks++) {
            const int koff = ks * 32;
            uint32_t ah[2][4], al[2][4];
            #pragma unroll
            for (int mt = 0; mt < 2; mt++) {
                const int row = wm + mt * 16 + (lane & 15);
                const uint32_t byt = (uint32_t)(row * 128 + koff + ((lane >> 4) << 4));
                ldm_x4(ah[mt][0], ah[mt][1], ah[mt][2], ah[mt][3], sAh + SWZ(byt));
                ldm_x4(al[mt][0], al[mt][1], al[mt][2], al[mt][3], sAl + SWZ(byt));
            }
            #pragma unroll
            for (int nt = 0; nt < 8; nt++) {
                const int row = wn + nt * 8 + (lane & 7);
                const uint32_t byt = (uint32_t)(row * 128 + koff + (((lane >> 3) & 1) << 4));
                uint32_t bh0, bh1, bl0, bl1;
                ldm_x2(bh0, bh1, sBh + SWZ(byt));
                ldm_x2(bl0, bl1, sBl + SWZ(byt));
                #pragma unroll
                for (int mt = 0; mt < 2; mt++) {
                    mma16816(acc[mt][nt], ah[mt], bh0, bh1);
                    mma16816(acc[mt][nt], ah[mt], bl0, bl1);
                    mma16816(acc[mt][nt], al[mt], bh0, bh1);
                }
            }
        }
        __syncthreads();
        if (ch + 3 < 16) issue(ch + 3, st);
    }

    // epilogue: RoPE, Q-scale, split, write hi/lo planes
    const int g = lane >> 2;
    const int q2 = (lane & 3) * 2;
    #pragma unroll
    for (int mt = 0; mt < 2; mt++) {
        #pragma unroll
        for (int rr = 0; rr < 2; rr++) {
            const int row = bm + wm + mt * 16 + g + rr * 8;
            const int bb = row >> 11;
            const int ss = row & 2047;
            #pragma unroll
            for (int nt = 0; nt < 8; nt++) {
                const int c = bn + wn + nt * 8 + q2;
                const int h = c >> 6;
                const int d = c & 63;
                const float sn = sinT[ss * (HD_/2) + (d >> 1)];
                const float cs = cosT[ss * (HD_/2) + (d >> 1)];
                const float e = acc[mt][nt][rr * 2 + 0];
                const float o = acc[mt][nt][rr * 2 + 1];
                const float wx = (e * cs - o * sn) * qscale;
                const float wy = (o * cs + e * sn) * qscale;
                __nv_bfloat16 hx, lx, hy, ly;
                split_bf16(wx, hx, lx); split_bf16(wy, hy, ly);
                const size_t ob = ((size_t)(bb * H_ + h) * S_ + ss) * HD_ + d;
                *(__nv_bfloat162*)&OutH[ob] = __nv_bfloat162(hx, hy);
                *(__nv_bfloat162*)&OutL[ob] = __nv_bfloat162(lx, ly);
            }
        }
    }
}

// ===========================================================================
// Kernel 2: flash attention, cp.async pipelined, V via ldmatrix.trans.
//   BQ=128 (8 warps x 16 rows), kt tiles of 64, 3-stage KV (32KB/stage).
// smem: Qh,Ql [128][64] 16KB each (32KB) + 3 x {Kh,Kl,Vh,Vl 8KB each} (96KB)
// ===========================================================================
#define ATT_SMEM (32768 + 3 * 32768)

__global__ __launch_bounds__(256)
void attn_hmma_kernel(float* __restrict__ Out)
{
    extern __shared__ char smem[];
    const uint32_t sbase = smem_u32(smem);
    const int tid = threadIdx.x;
    const int wid = tid >> 5;
    const int lane = tid & 31;
    const int g = lane >> 2;
    const int q2 = (lane & 3) * 2;

    const int q0 = blockIdx.x * 128;
    const int h  = blockIdx.y;
    const int b  = blockIdx.z;
    const size_t hoff = (size_t)(b * H_ + h) * S_ * HD_;
    const __nv_bfloat16* Qhp = g_Qh + hoff;
    const __nv_bfloat16* Qlp = g_Ql + hoff;
    const __nv_bfloat16* planesKV[4] = {g_Kh + hoff, g_Kl + hoff, g_Vh + hoff, g_Vl + hoff};

    auto issueKV = [&](int kt, int st) {
        const uint32_t sb = sbase + 32768 + st * 32768;
        #pragma unroll
        for (int p = 0; p < 4; p++) {
            #pragma unroll
            for (int it = 0; it < 2; it++) {
                const int idx = it * 256 + tid;    // 512 per plane
                const int row = idx >> 3, ck = idx & 7;
                const void* src = planesKV[p] + (size_t)(kt * 64 + row) * HD_ + ck * 8;
                cpa16(sb + p * 8192 + SWZ((uint32_t)(row * 128 + ck * 16)), src);
            }
        }
        CPA_COMMIT();
    };

    // prologue: Q group + KV 0,1,2
    #pragma unroll
    for (int p = 0; p < 2; p++) {
        const __nv_bfloat16* qp = p ? Qlp : Qhp;
        #pragma unroll
        for (int it = 0; it < 4; it++) {
            const int idx = it * 256 + tid;        // 1024 per plane
            const int row = idx >> 3, ck = idx & 7;
            cpa16(sbase + p * 16384 + SWZ((uint32_t)(row * 128 + ck * 16)),
                  qp + (size_t)(q0 + row) * HD_ + ck * 8);
        }
    }
    CPA_COMMIT();
    issueKV(0, 0); issueKV(1, 1); issueKV(2, 2);

    CPA_WAIT(3);           // Q done
    __syncthreads();

    // Q fragments (held in registers for whole kernel)
    uint32_t qh[4][4], ql[4][4];
    #pragma unroll
    for (int ks = 0; ks < 4; ks++) {
        const int row = wid * 16 + (lane & 15);
        const uint32_t byt = (uint32_t)(row * 128 + ks * 32 + ((lane >> 4) << 4));
        ldm_x4(qh[ks][0], qh[ks][1], qh[ks][2], qh[ks][3], sbase + SWZ(byt));
        ldm_x4(ql[ks][0], ql[ks][1], ql[ks][2], ql[ks][3], sbase + 16384 + SWZ(byt));
    }

    float m_[2] = {-INFINITY, -INFINITY};
    float l_[2] = {0.f, 0.f};
    float o_acc[8][4];
    #pragma unroll
    for (int i = 0; i < 8; i++)
        #pragma unroll
        for (int j = 0; j < 4; j++) o_acc[i][j] = 0.f;

    for (int kt = 0; kt < 32; kt++) {
        if (kt < 30)      { CPA_WAIT(2); }
        else if (kt == 30){ CPA_WAIT(1); }
        else              { CPA_WAIT(0); }
        __syncthreads();

        const int st = kt % 3;
        const uint32_t sKh = sbase + 32768 + st * 32768;
        const uint32_t sKl = sKh + 8192;
        const uint32_t sVh = sKh + 16384;
        const uint32_t sVl = sKh + 24576;

        // ---- S = Q K^T ----
        float sc[8][4];
        #pragma unroll
        for (int i = 0; i < 8; i++)
            #pragma unroll
            for (int j = 0; j < 4; j++) sc[i][j] = 0.f;

        #pragma unroll
        for (int ks = 0; ks < 4; ks++) {
            #pragma unroll
            for (int nt = 0; nt < 8; nt++) {
                const int row = nt * 8 + (lane & 7);
                const uint32_t byt = (uint32_t)(row * 128 + ks * 32 + (((lane >> 3) & 1) << 4));
                uint32_t bh0, bh1, bl0, bl1;
                ldm_x2(bh0, bh1, sKh + SWZ(byt));
                ldm_x2(bl0, bl1, sKl + SWZ(byt));
                mma16816(sc[nt], qh[ks], bh0, bh1);
                mma16816(sc[nt], qh[ks], bl0, bl1);
                mma16816(sc[nt], ql[ks], bh0, bh1);
            }
        }

        // ---- online softmax (quad shuffles; rows warp-exclusive) ----
        #pragma unroll
        for (int tr = 0; tr < 2; tr++) {
            float tmax = -INFINITY;
            #pragma unroll
            for (int nt = 0; nt < 8; nt++)
                tmax = fmaxf(tmax, fmaxf(sc[nt][tr*2], sc[nt][tr*2+1]));
            tmax = fmaxf(tmax, __shfl_xor_sync(0xffffffffu, tmax, 1));
            tmax = fmaxf(tmax, __shfl_xor_sync(0xffffffffu, tmax, 2));
            const float mnew = fmaxf(m_[tr], tmax);
            const float corr = __expf(m_[tr] - mnew);
            m_[tr] = mnew;
            float rs = 0.f;
            #pragma unroll
            for (int nt = 0; nt < 8; nt++) {
                const float p0 = __expf(sc[nt][tr*2]   - mnew);
                const float p1 = __expf(sc[nt][tr*2+1] - mnew);
                sc[nt][tr*2] = p0; sc[nt][tr*2+1] = p1;
                rs += p0 + p1;
            }
            rs += __shfl_xor_sync(0xffffffffu, rs, 1);
            rs += __shfl_xor_sync(0xffffffffu, rs, 2);
            l_[tr] = l_[tr] * corr + rs;
            #pragma unroll
            for (int dt = 0; dt < 8; dt++) {
                o_acc[dt][tr*2]   *= corr;
                o_acc[dt][tr*2+1] *= corr;
            }
        }

        // ---- O += P V (P split in regs; V B-frags via trans ldmatrix) ----
        #pragma unroll
        for (int ks2 = 0; ks2 < 4; ks2++) {
            uint32_t aHf[4], aLf[4];
            #pragma unroll
            for (int half = 0; half < 2; half++) {
                const int nt = 2 * ks2 + half;
                __nv_bfloat16 h0,l0,h1,l1,h2,l2,h3,l3;
                split_bf16(sc[nt][0], h0,l0); split_bf16(sc[nt][1], h1,l1);
                split_bf16(sc[nt][2], h2,l2); split_bf16(sc[nt][3], h3,l3);
                aHf[half*2+0] = pack2(h0,h1);
                aHf[half*2+1] = pack2(h2,h3);
                aLf[half*2+0] = pack2(l0,l1);
                aLf[half*2+1] = pack2(l2,l3);
            }
            #pragma unroll
            for (int dt = 0; dt < 8; dt++) {
                const uint32_t byt = (uint32_t)((ks2*16 + (lane & 15)) * 128 + dt * 16);
                uint32_t bh0, bh1, bl0, bl1;
                ldm_x2t(bh0, bh1, sVh + SWZ(byt));
                ldm_x2t(bl0, bl1, sVl + SWZ(byt));
                mma16816(o_acc[dt], aHf, bh0, bh1);
                mma16816(o_acc[dt], aHf, bl0, bl1);
                mma16816(o_acc[dt], aLf, bh0, bh1);
            }
        }
        __syncthreads();
        if (kt + 3 < 32) issueKV(kt + 3, st);
    }

    // ---- epilogue ----
    #pragma unroll
    for (int tr = 0; tr < 2; tr++) {
        const int qrow = q0 + wid * 16 + g + tr * 8;
        const float inv = 1.f / l_[tr];
        #pragma unroll
        for (int dt = 0; dt < 8; dt++) {
            float2 w;
            w.x = o_acc[dt][tr*2]   * inv;
            w.y = o_acc[dt][tr*2+1] * inv;
            *(float2*)&Out[((size_t)b * S_ + qrow) * D_ + h * HD_ + dt * 8 + q2] = w;
        }
    }
}

// ---------------------------------------------------------------------------
extern "C" void kernel_launch(void* const* d_in, const int* in_sizes, int n_in,
                              void* d_out, int out_size)
{
    const float* X  = (const float*)d_in[0];
    const float* Wq = (const float*)d_in[1];
    const float* Wk = (const float*)d_in[2];
    const float* Wv = (const float*)d_in[3];
    const float* sn = (const float*)d_in[4];
    const float* cs = (const float*)d_in[5];
    float* out = (float*)d_out;

    split_x_kernel<<<M_ * D_ / 4 / 256, 256>>>(X);
    dim3 gw(16, 16, 3);
    transw_kernel<<<gw, 256>>>(Wq, Wk, Wv);

    cudaFuncSetAttribute(qkv_hmma_kernel, cudaFuncAttributeMaxDynamicSharedMemorySize, QKV_SMEM);
    dim3 g1(D_ / 128, M_ / 128, 3);
    qkv_hmma_kernel<<<g1, 256, QKV_SMEM>>>(sn, cs);

    cudaFuncSetAttribute(attn_hmma_kernel, cudaFuncAttributeMaxDynamicSharedMemorySize, ATT_SMEM);
    dim3 g2(S_ / 128, H_, B_);
    attn_hmma_kernel<<<g2, 256, ATT_SMEM>>>(out);
}

// round 5
// speedup vs baseline: 3.0114x; 1.0998x over previous
#include <cuda_runtime.h>
#include <cuda_bf16.h>
#include <math.h>
#include <stdint.h>

#define B_  2
#define S_  2048
#define D_  1024
#define H_  16
#define HD_ 64
#define M_  (B_*S_)   // 4096

// Pre-split bf16 planes (prep kernels)
__device__ __nv_bfloat16 g_Xh[M_*D_], g_Xl[M_*D_];               // X  [m][k]
__device__ __nv_bfloat16 g_Wth[3*D_*D_], g_Wtl[3*D_*D_];         // Wt [n][k] x3
// Rotated Q/K/V bf16 hi/lo planes, [B,H,S,HD] (Q pre-scaled by 0.125)
__device__ __nv_bfloat16 g_Qh[B_*H_*S_*HD_], g_Ql[B_*H_*S_*HD_];
__device__ __nv_bfloat16 g_Kh[B_*H_*S_*HD_], g_Kl[B_*H_*S_*HD_];
__device__ __nv_bfloat16 g_Vh[B_*H_*S_*HD_], g_Vl[B_*H_*S_*HD_];

// ===========================================================================
// helpers
// ===========================================================================
__device__ __forceinline__ uint32_t smem_u32(const void* p) {
    uint32_t a;
    asm("{ .reg .u64 t; cvta.to.shared.u64 t, %1; cvt.u32.u64 %0, t; }" : "=r"(a) : "l"(p));
    return a;
}
#define SWZ(off) ((off) ^ (((off) >> 3) & 0x70))

__device__ __forceinline__ void cpa16(uint32_t dst, const void* src) {
    asm volatile("cp.async.cg.shared.global [%0], [%1], 16;" :: "r"(dst), "l"(src));
}
#define CPA_COMMIT() asm volatile("cp.async.commit_group;" ::: "memory")
#define CPA_WAIT(n)  asm volatile("cp.async.wait_group %0;" :: "n"(n) : "memory")

__device__ __forceinline__ void ldm_x4(uint32_t& r0, uint32_t& r1, uint32_t& r2, uint32_t& r3, uint32_t a) {
    asm volatile("ldmatrix.sync.aligned.m8n8.x4.shared.b16 {%0,%1,%2,%3}, [%4];"
                 : "=r"(r0), "=r"(r1), "=r"(r2), "=r"(r3) : "r"(a));
}
__device__ __forceinline__ void ldm_x2(uint32_t& r0, uint32_t& r1, uint32_t a) {
    asm volatile("ldmatrix.sync.aligned.m8n8.x2.shared.b16 {%0,%1}, [%2];"
                 : "=r"(r0), "=r"(r1) : "r"(a));
}
__device__ __forceinline__ void ldm_x2t(uint32_t& r0, uint32_t& r1, uint32_t a) {
    asm volatile("ldmatrix.sync.aligned.m8n8.x2.trans.shared.b16 {%0,%1}, [%2];"
                 : "=r"(r0), "=r"(r1) : "r"(a));
}
__device__ __forceinline__ void mma16816(float* c, const uint32_t* a, uint32_t b0, uint32_t b1) {
    asm volatile(
        "mma.sync.aligned.m16n8k16.row.col.f32.bf16.bf16.f32 "
        "{%0,%1,%2,%3}, {%4,%5,%6,%7}, {%8,%9}, {%0,%1,%2,%3};"
        : "+f"(c[0]), "+f"(c[1]), "+f"(c[2]), "+f"(c[3])
        : "r"(a[0]), "r"(a[1]), "r"(a[2]), "r"(a[3]), "r"(b0), "r"(b1));
}
__device__ __forceinline__ void split_bf16(float x, __nv_bfloat16& h, __nv_bfloat16& l) {
    h = __float2bfloat16(x);
    l = __float2bfloat16(x - __bfloat162float(h));
}
__device__ __forceinline__ uint32_t pack2(__nv_bfloat16 e0, __nv_bfloat16 e1) {
    __nv_bfloat162 t(e0, e1);
    return *reinterpret_cast<uint32_t*>(&t);
}

// ===========================================================================
// Prep 1: split X into bf16 hi/lo planes (same [m][k] layout)
// ===========================================================================
__global__ __launch_bounds__(256) void split_x_kernel(const float* __restrict__ X)
{
    const int i = blockIdx.x * 256 + threadIdx.x;     // float4 index
    float4 v = ((const float4*)X)[i];
    __nv_bfloat16 h0, l0, h1, l1, h2, l2, h3, l3;
    split_bf16(v.x, h0, l0); split_bf16(v.y, h1, l1);
    split_bf16(v.z, h2, l2); split_bf16(v.w, h3, l3);
    ((__nv_bfloat162*)g_Xh)[i*2]   = __nv_bfloat162(h0, h1);
    ((__nv_bfloat162*)g_Xh)[i*2+1] = __nv_bfloat162(h2, h3);
    ((__nv_bfloat162*)g_Xl)[i*2]   = __nv_bfloat162(l0, l1);
    ((__nv_bfloat162*)g_Xl)[i*2+1] = __nv_bfloat162(l2, l3);
}

// ===========================================================================
// Prep 2: transpose + split W -> Wt[n][k] hi/lo. 64x64 tiles via smem.
// ===========================================================================
__global__ __launch_bounds__(256) void transw_kernel(
    const float* __restrict__ Wq, const float* __restrict__ Wk, const float* __restrict__ Wv)
{
    __shared__ float tile[64][65];
    const int w = blockIdx.z;
    const float* W = (w == 0) ? Wq : (w == 1 ? Wk : Wv);
    const int k0 = blockIdx.x * 64;
    const int n0 = blockIdx.y * 64;
    const int tid = threadIdx.x;

    #pragma unroll
    for (int it = 0; it < 4; it++) {
        const int idx = it * 256 + tid;
        const int r = idx >> 4, c4 = (idx & 15) << 2;
        float4 v = *(const float4*)&W[(size_t)(k0 + r) * D_ + n0 + c4];
        tile[r][c4] = v.x; tile[r][c4+1] = v.y; tile[r][c4+2] = v.z; tile[r][c4+3] = v.w;
    }
    __syncthreads();
    __nv_bfloat16* Oh = g_Wth + (size_t)w * D_ * D_;
    __nv_bfloat16* Ol = g_Wtl + (size_t)w * D_ * D_;
    #pragma unroll
    for (int it = 0; it < 4; it++) {
        const int idx = it * 256 + tid;
        const int rn = idx >> 4, kc4 = (idx & 15) << 2;
        __nv_bfloat16 h[4], l[4];
        #pragma unroll
        for (int e = 0; e < 4; e++) split_bf16(tile[kc4 + e][rn], h[e], l[e]);
        const size_t o = (size_t)(n0 + rn) * D_ + k0 + kc4;
        *(__nv_bfloat162*)&Oh[o]   = __nv_bfloat162(h[0], h[1]);
        *(__nv_bfloat162*)&Oh[o+2] = __nv_bfloat162(h[2], h[3]);
        *(__nv_bfloat162*)&Ol[o]   = __nv_bfloat162(l[0], l[1]);
        *(__nv_bfloat162*)&Ol[o+2] = __nv_bfloat162(l[2], l[3]);
    }
}

// ===========================================================================
// Kernel 1: QKV GEMM, cp.async 2-stage pipeline + RoPE epilogue.
//   Tile 128x64, BK=64 chunks x16. Stage = Ah(16K) Al(16K) Bh(8K) Bl(8K) = 48KB
//   2 stages = 96KB -> 2 CTAs/SM. 8 warps: 4m x 2n, warp tile 32x32.
// ===========================================================================
#define QKV_STAGE 49152
#define QKV_SMEM (2 * QKV_STAGE)

__global__ __launch_bounds__(256, 2)
void qkv_hmma_kernel(const float* __restrict__ sinT, const float* __restrict__ cosT)
{
    extern __shared__ char smem[];
    const uint32_t sbase = smem_u32(smem);
    const int tid = threadIdx.x;
    const int wid = tid >> 5;
    const int lane = tid & 31;
    const int wm = (wid >> 1) * 32;    // 0,32,64,96
    const int wn = (wid & 1) * 32;     // 0,32

    const int which = blockIdx.z;
    const int bm = blockIdx.y * 128;
    const int bn = blockIdx.x * 64;
    const __nv_bfloat16* Bth = g_Wth + (size_t)which * D_ * D_;
    const __nv_bfloat16* Btl = g_Wtl + (size_t)which * D_ * D_;
    __nv_bfloat16* OutH = (which == 0) ? g_Qh : (which == 1 ? g_Kh : g_Vh);
    __nv_bfloat16* OutL = (which == 0) ? g_Ql : (which == 1 ? g_Kl : g_Vl);
    const float qscale = (which == 0) ? 0.125f : 1.0f;

    // stage layout: Ah[0,16K) Al[16K,32K) Bh[32K,40K) Bl[40K,48K)
    auto issue = [&](int ch, int st) {
        const uint32_t sb = sbase + st * QKV_STAGE;
        // A planes: 128 rows x 64 k -> 1024 cpa16 per plane
        #pragma unroll
        for (int p = 0; p < 2; p++) {
            const __nv_bfloat16* src = p ? g_Xl : g_Xh;
            #pragma unroll
            for (int it = 0; it < 4; it++) {
                const int idx = it * 256 + tid;
                const int row = idx >> 3, ck = idx & 7;
                cpa16(sb + p * 16384 + SWZ((uint32_t)(row * 128 + ck * 16)),
                      src + (size_t)(bm + row) * D_ + ch * 64 + ck * 8);
            }
        }
        // B planes: 64 rows x 64 k -> 512 cpa16 per plane
        #pragma unroll
        for (int p = 0; p < 2; p++) {
            const __nv_bfloat16* src = p ? Btl : Bth;
            #pragma unroll
            for (int it = 0; it < 2; it++) {
                const int idx = it * 256 + tid;
                const int row = idx >> 3, ck = idx & 7;
                cpa16(sb + 32768 + p * 8192 + SWZ((uint32_t)(row * 128 + ck * 16)),
                      src + (size_t)(bn + row) * D_ + ch * 64 + ck * 8);
            }
        }
        CPA_COMMIT();
    };

    float acc[2][4][4];
    #pragma unroll
    for (int i = 0; i < 2; i++)
        #pragma unroll
        for (int j = 0; j < 4; j++)
            #pragma unroll
            for (int k = 0; k < 4; k++) acc[i][j][k] = 0.f;

    issue(0, 0); issue(1, 1);

    for (int ch = 0; ch < 16; ch++) {
        if (ch < 15) { CPA_WAIT(1); } else { CPA_WAIT(0); }
        __syncthreads();

        const int st = ch & 1;
        const uint32_t sAh = sbase + st * QKV_STAGE;
        const uint32_t sAl = sAh + 16384;
        const uint32_t sBh = sAh + 32768;
        const uint32_t sBl = sAh + 40960;

        #pragma unroll
        for (int ks = 0; ks < 4; ks++) {
            const int koff = ks * 32;
            uint32_t ah[2][4], al[2][4];
            #pragma unroll
            for (int mt = 0; mt < 2; mt++) {
                const int row = wm + mt * 16 + (lane & 15);
                const uint32_t byt = (uint32_t)(row * 128 + koff + ((lane >> 4) << 4));
                ldm_x4(ah[mt][0], ah[mt][1], ah[mt][2], ah[mt][3], sAh + SWZ(byt));
                ldm_x4(al[mt][0], al[mt][1], al[mt][2], al[mt][3], sAl + SWZ(byt));
            }
            #pragma unroll
            for (int nt = 0; nt < 4; nt++) {
                const int row = wn + nt * 8 + (lane & 7);
                const uint32_t byt = (uint32_t)(row * 128 + koff + (((lane >> 3) & 1) << 4));
                uint32_t bh0, bh1, bl0, bl1;
                ldm_x2(bh0, bh1, sBh + SWZ(byt));
                ldm_x2(bl0, bl1, sBl + SWZ(byt));
                #pragma unroll
                for (int mt = 0; mt < 2; mt++) {
                    mma16816(acc[mt][nt], ah[mt], bh0, bh1);
                    mma16816(acc[mt][nt], ah[mt], bl0, bl1);
                    mma16816(acc[mt][nt], al[mt], bh0, bh1);
                }
            }
        }
        __syncthreads();
        if (ch + 2 < 16) issue(ch + 2, st);
    }

    // epilogue: RoPE, Q-scale, split, write hi/lo planes
    const int g = lane >> 2;
    const int q2 = (lane & 3) * 2;
    #pragma unroll
    for (int mt = 0; mt < 2; mt++) {
        #pragma unroll
        for (int rr = 0; rr < 2; rr++) {
            const int row = bm + wm + mt * 16 + g + rr * 8;
            const int bb = row >> 11;
            const int ss = row & 2047;
            #pragma unroll
            for (int nt = 0; nt < 4; nt++) {
                const int c = bn + wn + nt * 8 + q2;
                const int h = c >> 6;
                const int d = c & 63;
                const float sn = sinT[ss * (HD_/2) + (d >> 1)];
                const float cs = cosT[ss * (HD_/2) + (d >> 1)];
                const float e = acc[mt][nt][rr * 2 + 0];
                const float o = acc[mt][nt][rr * 2 + 1];
                const float wx = (e * cs - o * sn) * qscale;
                const float wy = (o * cs + e * sn) * qscale;
                __nv_bfloat16 hx, lx, hy, ly;
                split_bf16(wx, hx, lx); split_bf16(wy, hy, ly);
                const size_t ob = ((size_t)(bb * H_ + h) * S_ + ss) * HD_ + d;
                *(__nv_bfloat162*)&OutH[ob] = __nv_bfloat162(hx, hy);
                *(__nv_bfloat162*)&OutL[ob] = __nv_bfloat162(lx, ly);
            }
        }
    }
}

// ===========================================================================
// Kernel 2: flash attention, cp.async 2-stage KV pipeline, 2 CTAs/SM.
//   BQ=128 (8 warps x 16 rows), kt tiles of 64.
// smem: Qh,Ql 16KB each (32KB) + 2 x {Kh,Kl,Vh,Vl 8KB each} (64KB) = 96KB
// ===========================================================================
#define ATT_SMEM (32768 + 2 * 32768)

__global__ __launch_bounds__(256, 2)
void attn_hmma_kernel(float* __restrict__ Out)
{
    extern __shared__ char smem[];
    const uint32_t sbase = smem_u32(smem);
    const int tid = threadIdx.x;
    const int wid = tid >> 5;
    const int lane = tid & 31;
    const int g = lane >> 2;
    const int q2 = (lane & 3) * 2;

    const int q0 = blockIdx.x * 128;
    const int h  = blockIdx.y;
    const int b  = blockIdx.z;
    const size_t hoff = (size_t)(b * H_ + h) * S_ * HD_;
    const __nv_bfloat16* Qhp = g_Qh + hoff;
    const __nv_bfloat16* Qlp = g_Ql + hoff;
    const __nv_bfloat16* planesKV[4] = {g_Kh + hoff, g_Kl + hoff, g_Vh + hoff, g_Vl + hoff};

    auto issueKV = [&](int kt, int st) {
        const uint32_t sb = sbase + 32768 + st * 32768;
        #pragma unroll
        for (int p = 0; p < 4; p++) {
            #pragma unroll
            for (int it = 0; it < 2; it++) {
                const int idx = it * 256 + tid;    // 512 per plane
                const int row = idx >> 3, ck = idx & 7;
                cpa16(sb + p * 8192 + SWZ((uint32_t)(row * 128 + ck * 16)),
                      planesKV[p] + (size_t)(kt * 64 + row) * HD_ + ck * 8);
            }
        }
        CPA_COMMIT();
    };

    // prologue: Q group + KV 0,1
    #pragma unroll
    for (int p = 0; p < 2; p++) {
        const __nv_bfloat16* qp = p ? Qlp : Qhp;
        #pragma unroll
        for (int it = 0; it < 4; it++) {
            const int idx = it * 256 + tid;
            const int row = idx >> 3, ck = idx & 7;
            cpa16(sbase + p * 16384 + SWZ((uint32_t)(row * 128 + ck * 16)),
                  qp + (size_t)(q0 + row) * HD_ + ck * 8);
        }
    }
    CPA_COMMIT();
    issueKV(0, 0); issueKV(1, 1);

    CPA_WAIT(2);           // Q done
    __syncthreads();

    // Q fragments (held in registers for whole kernel)
    uint32_t qh[4][4], ql[4][4];
    #pragma unroll
    for (int ks = 0; ks < 4; ks++) {
        const int row = wid * 16 + (lane & 15);
        const uint32_t byt = (uint32_t)(row * 128 + ks * 32 + ((lane >> 4) << 4));
        ldm_x4(qh[ks][0], qh[ks][1], qh[ks][2], qh[ks][3], sbase + SWZ(byt));
        ldm_x4(ql[ks][0], ql[ks][1], ql[ks][2], ql[ks][3], sbase + 16384 + SWZ(byt));
    }

    float m_[2] = {-INFINITY, -INFINITY};
    float l_[2] = {0.f, 0.f};
    float o_acc[8][4];
    #pragma unroll
    for (int i = 0; i < 8; i++)
        #pragma unroll
        for (int j = 0; j < 4; j++) o_acc[i][j] = 0.f;

    for (int kt = 0; kt < 32; kt++) {
        if (kt < 31) { CPA_WAIT(1); } else { CPA_WAIT(0); }
        __syncthreads();

        const int st = kt & 1;
        const uint32_t sKh = sbase + 32768 + st * 32768;
        const uint32_t sKl = sKh + 8192;
        const uint32_t sVh = sKh + 16384;
        const uint32_t sVl = sKh + 24576;

        // ---- S = Q K^T ----
        float sc[8][4];
        #pragma unroll
        for (int i = 0; i < 8; i++)
            #pragma unroll
            for (int j = 0; j < 4; j++) sc[i][j] = 0.f;

        #pragma unroll
        for (int ks = 0; ks < 4; ks++) {
            #pragma unroll
            for (int nt = 0; nt < 8; nt++) {
                const int row = nt * 8 + (lane & 7);
                const uint32_t byt = (uint32_t)(row * 128 + ks * 32 + (((lane >> 3) & 1) << 4));
                uint32_t bh0, bh1, bl0, bl1;
                ldm_x2(bh0, bh1, sKh + SWZ(byt));
                ldm_x2(bl0, bl1, sKl + SWZ(byt));
                mma16816(sc[nt], qh[ks], bh0, bh1);
                mma16816(sc[nt], qh[ks], bl0, bl1);
                mma16816(sc[nt], ql[ks], bh0, bh1);
            }
        }

        // ---- online softmax (quad shuffles; rows warp-exclusive) ----
        #pragma unroll
        for (int tr = 0; tr < 2; tr++) {
            float tmax = -INFINITY;
            #pragma unroll
            for (int nt = 0; nt < 8; nt++)
                tmax = fmaxf(tmax, fmaxf(sc[nt][tr*2], sc[nt][tr*2+1]));
            tmax = fmaxf(tmax, __shfl_xor_sync(0xffffffffu, tmax, 1));
            tmax = fmaxf(tmax, __shfl_xor_sync(0xffffffffu, tmax, 2));
            const float mnew = fmaxf(m_[tr], tmax);
            const float corr = __expf(m_[tr] - mnew);
            m_[tr] = mnew;
            float rs = 0.f;
            #pragma unroll
            for (int nt = 0; nt < 8; nt++) {
                const float p0 = __expf(sc[nt][tr*2]   - mnew);
                const float p1 = __expf(sc[nt][tr*2+1] - mnew);
                sc[nt][tr*2] = p0; sc[nt][tr*2+1] = p1;
                rs += p0 + p1;
            }
            rs += __shfl_xor_sync(0xffffffffu, rs, 1);
            rs += __shfl_xor_sync(0xffffffffu, rs, 2);
            l_[tr] = l_[tr] * corr + rs;
            #pragma unroll
            for (int dt = 0; dt < 8; dt++) {
                o_acc[dt][tr*2]   *= corr;
                o_acc[dt][tr*2+1] *= corr;
            }
        }

        // ---- O += P V (P split in regs; V B-frags via trans ldmatrix) ----
        #pragma unroll
        for (int ks2 = 0; ks2 < 4; ks2++) {
            uint32_t aHf[4], aLf[4];
            #pragma unroll
            for (int half = 0; half < 2; half++) {
                const int nt = 2 * ks2 + half;
                __nv_bfloat16 h0,l0,h1,l1,h2,l2,h3,l3;
                split_bf16(sc[nt][0], h0,l0); split_bf16(sc[nt][1], h1,l1);
                split_bf16(sc[nt][2], h2,l2); split_bf16(sc[nt][3], h3,l3);
                aHf[half*2+0] = pack2(h0,h1);
                aHf[half*2+1] = pack2(h2,h3);
                aLf[half*2+0] = pack2(l0,l1);
                aLf[half*2+1] = pack2(l2,l3);
            }
            #pragma unroll
            for (int dt = 0; dt < 8; dt++) {
                const uint32_t byt = (uint32_t)((ks2*16 + (lane & 15)) * 128 + dt * 16);
                uint32_t bh0, bh1, bl0, bl1;
                ldm_x2t(bh0, bh1, sVh + SWZ(byt));
                ldm_x2t(bl0, bl1, sVl + SWZ(byt));
                mma16816(o_acc[dt], aHf, bh0, bh1);
                mma16816(o_acc[dt], aHf, bl0, bl1);
                mma16816(o_acc[dt], aLf, bh0, bh1);
            }
        }
        __syncthreads();
        if (kt + 2 < 32) issueKV(kt + 2, st);
    }

    // ---- epilogue ----
    #pragma unroll
    for (int tr = 0; tr < 2; tr++) {
        const int qrow = q0 + wid * 16 + g + tr * 8;
        const float inv = 1.f / l_[tr];
        #pragma unroll
        for (int dt = 0; dt < 8; dt++) {
            float2 w;
            w.x = o_acc[dt][tr*2]   * inv;
            w.y = o_acc[dt][tr*2+1] * inv;
            *(float2*)&Out[((size_t)b * S_ + qrow) * D_ + h * HD_ + dt * 8 + q2] = w;
        }
    }
}

// ---------------------------------------------------------------------------
extern "C" void kernel_launch(void* const* d_in, const int* in_sizes, int n_in,
                              void* d_out, int out_size)
{
    const float* X  = (const float*)d_in[0];
    const float* Wq = (const float*)d_in[1];
    const float* Wk = (const float*)d_in[2];
    const float* Wv = (const float*)d_in[3];
    const float* sn = (const float*)d_in[4];
    const float* cs = (const float*)d_in[5];
    float* out = (float*)d_out;

    split_x_kernel<<<M_ * D_ / 4 / 256, 256>>>(X);
    dim3 gw(16, 16, 3);
    transw_kernel<<<gw, 256>>>(Wq, Wk, Wv);

    cudaFuncSetAttribute(qkv_hmma_kernel, cudaFuncAttributeMaxDynamicSharedMemorySize, QKV_SMEM);
    dim3 g1(D_ / 64, M_ / 128, 3);   // (16, 32, 3)
    qkv_hmma_kernel<<<g1, 256, QKV_SMEM>>>(sn, cs);

    cudaFuncSetAttribute(attn_hmma_kernel, cudaFuncAttributeMaxDynamicSharedMemorySize, ATT_SMEM);
    dim3 g2(S_ / 128, H_, B_);       // (16, 16, 2)
    attn_hmma_kernel<<<g2, 256, ATT_SMEM>>>(out);
}